// round 6
// baseline (speedup 1.0000x reference)
#include <cuda_runtime.h>

// ComNet: R=64 runs, T=256 timesteps, N=1024 agents, MLP 4->10(tanh)->2.
// Wavefront over B=4 agent blocks: thread t computes block b = s - 2t at step
// s. One CTA per run. Intra-warp handoff via shuffles; warp boundary via
// 3-deep smem ring + one __syncthreads per step.
// MLP math uses packed fma.rn.f32x2 (FFMA2): hidden units paired 2-wide,
// W2 outputs (o0,o1) accumulated as packed pairs. tanh via MUFU.TANH.

#define R_ 64
#define T_ 256
#define N_ 1024
#define NB_ 256                       // blocks per row (N/4)
#define NSTEP_ (2 * (T_ - 1) + NB_)   // 766 wavefront steps

typedef unsigned long long ull;

__device__ __forceinline__ float htanh(float x) {
    float r; asm("tanh.approx.f32 %0, %1;" : "=f"(r) : "f"(x)); return r;
}
__device__ __forceinline__ ull pk(float lo, float hi) {
    ull r; asm("mov.b64 %0, {%1, %2};" : "=l"(r) : "f"(lo), "f"(hi)); return r;
}
__device__ __forceinline__ void upk(float& lo, float& hi, ull v) {
    asm("mov.b64 {%0, %1}, %2;" : "=f"(lo), "=f"(hi) : "l"(v));
}
__device__ __forceinline__ ull fma2(ull a, ull b, ull c) {
    ull d; asm("fma.rn.f32x2 %0, %1, %2, %3;" : "=l"(d) : "l"(a), "l"(b), "l"(c));
    return d;
}

__global__ __launch_bounds__(256, 1)
void comnet_kernel(const float* __restrict__ runs,
                   const float* __restrict__ comm0,
                   const float* __restrict__ w1,
                   const float* __restrict__ b1,
                   const float* __restrict__ w2,
                   const float* __restrict__ b2,
                   float* __restrict__ out)
{
    const int r    = blockIdx.x;
    const int t    = threadIdx.x;
    const int lane = t & 31;
    const int warp = t >> 5;

    // 3-deep ring for warp-boundary block exchange (lane31 -> next warp lane0)
    __shared__ float4 ring[3][8];

    // ---- packed weights in registers ----
    // pair p = hidden units (2p, 2p+1)
    ull W1p[20], B1p[5], W2a[5], W2b[5];
#pragma unroll
    for (int p = 0; p < 5; ++p) {
#pragma unroll
        for (int q = 0; q < 4; ++q)
            W1p[4 * p + q] = pk(w1[4 * (2 * p) + q], w1[4 * (2 * p + 1) + q]);
        B1p[p] = pk(b1[2 * p], b1[2 * p + 1]);
        W2a[p] = pk(w2[2 * p],      w2[2 * p + 1]);        // output row 0
        W2b[p] = pk(w2[10 + 2 * p], w2[10 + 2 * p + 1]);   // output row 1
    }
    const ull B2lo0 = pk(b2[0], 0.0f);
    const ull B2hi0 = pk(b2[1], 0.0f);

    const float4* __restrict__ xrow4 =
        (const float4*)(runs + ((size_t)r * T_ + t) * (size_t)N_ * 2);
    float4* __restrict__ orow4 = (float4*)(out + ((size_t)r * T_ + t) * N_);
    const float* __restrict__ c0row = comm0 + (size_t)r * N_;

    float4 h1 = make_float4(0.f, 0.f, 0.f, 0.f);   // own block @ s-1
    float4 h2 = h1;                                // own block @ s-2

    // prefetch buffers (first active block is b=0 at s=2t)
    float4 px0 = h1, px1 = h1, pc0 = h1;
    if (t == 0) {
        px0 = xrow4[0];
        px1 = xrow4[1];
        pc0 = make_float4(c0row[1], c0row[2], c0row[3], c0row[4]);
    }

    // rotating ring phases: p2=(s-2)%3, p1=(s-1)%3, p0=s%3
    int p0 = 0, p1 = 2, p2 = 1;

    for (int s = 0; s < NSTEP_; ++s) {
        const int b = s - 2 * t;
        const bool active = ((unsigned)b < (unsigned)NB_);

        // ---- right values c(t-1, 4b+1..4b+4) ----
        float r0 = __shfl_up_sync(0xffffffffu, h2.y, 1);
        float r1 = __shfl_up_sync(0xffffffffu, h2.z, 1);
        float r2 = __shfl_up_sync(0xffffffffu, h2.w, 1);
        float r3 = __shfl_up_sync(0xffffffffu, h1.x, 1);
        if (lane == 0) {
            const int pw = (warp > 0) ? (warp - 1) : 0;
            float4 g2 = ring[p2][pw];   // producer block @ s-2
            float4 g1 = ring[p1][pw];   // producer block @ s-1
            r0 = g2.y; r1 = g2.z; r2 = g2.w; r3 = g1.x;
        }
        if (t == 0) { r0 = pc0.x; r1 = pc0.y; r2 = pc0.z; r3 = pc0.w; }
        if (b == NB_ - 1) r3 = 0.0f;    // zero right boundary for agent N-1

        const float4 cx0 = px0, cx1 = px1;

        // ---- prefetch next step's block inputs ----
        const int bn = s + 1 - 2 * t;
        if ((unsigned)bn < (unsigned)NB_) {
            px0 = xrow4[2 * bn];
            px1 = xrow4[2 * bn + 1];
            if (t == 0) {
                const int base = 4 * bn;
                pc0 = make_float4(c0row[base + 1], c0row[base + 2],
                                  c0row[base + 3],
                                  (bn < NB_ - 1) ? c0row[base + 4] : 0.0f);
            }
        }

        float4 cur = h1;
        if (active) {
            float o0v[4], o1v[4];
            float lf = (b == 0) ? 0.0f : h1.w;     // c(t, 4b-1)
#pragma unroll
            for (int k = 0; k < 4; ++k) {
                const float xx = (k == 0) ? cx0.x : (k == 1) ? cx0.z
                                : (k == 2) ? cx1.x : cx1.z;
                const float xy = (k == 0) ? cx0.y : (k == 1) ? cx0.w
                                : (k == 2) ? cx1.y : cx1.w;
                const float rt = (k == 0) ? r0 : (k == 1) ? r1
                                : (k == 2) ? r2 : r3;

                const ull xx2 = pk(xx, xx);
                const ull xy2 = pk(xy, xy);
                const ull rt2 = pk(rt, rt);
                const ull lf2 = pk(lf, lf);

                ull A0 = B2lo0, A1 = B2hi0;
#pragma unroll
                for (int p = 0; p < 5; ++p) {
                    ull a = fma2(W1p[4 * p + 0], xx2, B1p[p]);
                    a     = fma2(W1p[4 * p + 1], xy2, a);
                    a     = fma2(W1p[4 * p + 3], rt2, a);
                    a     = fma2(W1p[4 * p + 2], lf2, a);   // lf last: shortest chain
                    float alo, ahi; upk(alo, ahi, a);
                    const ull hh = pk(htanh(alo), htanh(ahi));
                    A0 = fma2(W2a[p], hh, A0);
                    A1 = fma2(W2b[p], hh, A1);
                }
                float a0l, a0h, a1l, a1h;
                upk(a0l, a0h, A0);
                upk(a1l, a1h, A1);
                o0v[k] = a0l + a0h;
                const float o1 = a1l + a1h;
                o1v[k] = o1;
                lf = o1;                           // left-chain within block
            }
            orow4[b] = make_float4(o0v[0], o0v[1], o0v[2], o0v[3]);
            cur = make_float4(o1v[0], o1v[1], o1v[2], o1v[3]);
        }

        // publish warp-boundary block; shift history
        if (lane == 31 && active) ring[p0][warp] = cur;
        h2 = h1;
        if (active) h1 = cur;

        // rotate ring phases
        const int pn = p2;
        p2 = p1; p1 = p0; p0 = pn;

        __syncthreads();
    }
}

extern "C" void kernel_launch(void* const* d_in, const int* in_sizes, int n_in,
                              void* d_out, int out_size)
{
    const float* runs  = (const float*)d_in[0];
    const float* comm0 = (const float*)d_in[1];
    const float* w1    = (const float*)d_in[2];
    const float* b1    = (const float*)d_in[3];
    const float* w2    = (const float*)d_in[4];
    const float* b2    = (const float*)d_in[5];
    float* out = (float*)d_out;

    comnet_kernel<<<R_, T_>>>(runs, comm0, w1, b1, w2, b2, out);
}